// round 1
// baseline (speedup 1.0000x reference)
#include <cuda_runtime.h>
#include <cstdint>
#include <cstddef>

// CombineGraph: h = emb[inputs]; e_k = leakyrelu(einsum(bid,bjd,d->bij; h,h,a_k));
// alpha = softmax(select_by_adj(e_k, mask -9e15)); out = alpha @ h.
// B=512, L=100, D=128. One CTA per batch, tf32 mma.sync GEMMs.

#define B_    512
#define L_    100
#define D_    128
#define HS    132      // h / ha row stride (floats): conflict-free fragments
#define AS    108      // alpha row stride (floats): conflict-free fragments
#define ADJS  104      // adj row stride (bytes)
#define MROWS 112      // padded M rows (7 x m16)
#define NEG_INF_ -9e15f

__device__ __forceinline__ float rna_tf32(float x) {
    unsigned u;
    asm("cvt.rna.tf32.f32 %0, %1;" : "=r"(u) : "f"(x));
    return __uint_as_float(u);
}

__device__ __forceinline__ void mma_tf32(float* c, const unsigned* a, unsigned b0, unsigned b1) {
    asm volatile(
        "mma.sync.aligned.m16n8k8.row.col.f32.tf32.tf32.f32 "
        "{%0,%1,%2,%3},{%4,%5,%6,%7},{%8,%9},{%0,%1,%2,%3};\n"
        : "+f"(c[0]), "+f"(c[1]), "+f"(c[2]), "+f"(c[3])
        : "r"(a[0]), "r"(a[1]), "r"(a[2]), "r"(a[3]), "r"(b0), "r"(b1));
}

__global__ __launch_bounds__(512, 1)
void combine_graph_kernel(const int* __restrict__ inputs,
                          const int* __restrict__ adj,
                          const float* __restrict__ emb,
                          const float* __restrict__ a0p,
                          const float* __restrict__ a1p,
                          const float* __restrict__ a2p,
                          const float* __restrict__ a3p,
                          float* __restrict__ out)
{
    extern __shared__ char smem_raw[];
    float* h_sm   = (float*)smem_raw;              // 104 x 132
    float* ha_sm  = h_sm  + 104 * HS;              // 112 x 132
    float* al_sm  = ha_sm + MROWS * HS;            // 112 x 108
    float* a_sm   = al_sm + MROWS * AS;            // 4 x 128
    char*  adj_sm = (char*)(a_sm + 4 * 128);       // 100 x 104 (int8)

    const int b    = blockIdx.x;
    const int tid  = threadIdx.x;
    const int w    = tid >> 5;
    const int lane = tid & 31;
    const int g    = lane >> 2;    // groupID (0..7)
    const int t4   = lane & 3;     // threadID_in_group (0..3)

    const int* inp  = inputs + b * L_;
    const int* adjb = adj + (size_t)b * (L_ * L_);

    // ---------------- phase 0: loads ----------------
    {   // a vectors (4 x 128, one value per thread)
        int k = tid >> 7, d = tid & 127;
        const float* ap = (k == 0) ? a0p : (k == 1) ? a1p : (k == 2) ? a2p : a3p;
        a_sm[k * 128 + d] = ap[d];
    }
    // embedding gather -> h_sm (tf32-rounded); rows 100..103 zero
    for (int e = tid; e < 104 * 32; e += 512) {
        int r = e >> 5, q = e & 31;
        float4 v = make_float4(0.f, 0.f, 0.f, 0.f);
        if (r < L_) {
            int id = inp[r];
            const float4* src = (const float4*)(emb + (size_t)id * D_);
            v = src[q];
            v.x = rna_tf32(v.x); v.y = rna_tf32(v.y);
            v.z = rna_tf32(v.z); v.w = rna_tf32(v.w);
        }
        *(float4*)(h_sm + r * HS + q * 4) = v;
    }
    // adj -> int8 shared
    for (int e = tid; e < 2500; e += 512) {
        int i = e / 25, c = e % 25;
        int4 v = ((const int4*)(adjb + i * 100))[c];
        unsigned p = (unsigned)(v.x & 0xff) | ((unsigned)(v.y & 0xff) << 8)
                   | ((unsigned)(v.z & 0xff) << 16) | ((unsigned)(v.w & 0xff) << 24);
        *(unsigned*)(adj_sm + i * ADJS + c * 4) = p;
    }
    if (tid < L_) *(unsigned*)(adj_sm + tid * ADJS + 100) = 0u;  // pad cols 100..103
    // alpha logits init to -inf
    for (int e = tid; e < MROWS * AS; e += 512) al_sm[e] = NEG_INF_;
    __syncthreads();

    // ---------------- phase 1: GEMM1 (4 passes, one per edge type) ----------------
    const int it32 = w & 3;              // 32-row M tile
    const int row0 = it32 * 32;
    const int nh   = (it32 == 3) ? 1 : 2;   // it32==3 covers rows 96..111 only
    const int jt0  = w >> 2;

    for (int k = 0; k < 4; ++k) {
        // ha = h * a_k (rows >= 104 zero)
        for (int e = tid; e < MROWS * 32; e += 512) {
            int r = e >> 5, q = (e & 31) * 4;
            float4 v = make_float4(0.f, 0.f, 0.f, 0.f);
            if (r < 104) {
                float4 hv = *(float4*)(h_sm + r * HS + q);
                float4 av = *(float4*)(a_sm + k * 128 + q);
                v.x = hv.x * av.x; v.y = hv.y * av.y;
                v.z = hv.z * av.z; v.w = hv.w * av.w;
            }
            *(float4*)(ha_sm + r * HS + q) = v;
        }
        __syncthreads();

        float c[4][2][4];
        #pragma unroll
        for (int m = 0; m < 4; ++m)
            #pragma unroll
            for (int h = 0; h < 2; ++h)
                #pragma unroll
                for (int r = 0; r < 4; ++r) c[m][h][r] = 0.f;

        for (int kc = 0; kc < 8; ++kc) {       // k-dim: 16 kt, chunks of 2
            unsigned A[2][2][4];
            #pragma unroll
            for (int kk = 0; kk < 2; ++kk) {
                int col = (2 * kc + kk) * 8 + t4;
                #pragma unroll
                for (int h = 0; h < 2; ++h) {
                    if (h < nh) {
                        int r = row0 + h * 16 + g;
                        A[kk][h][0] = __float_as_uint(ha_sm[r * HS + col]);
                        A[kk][h][1] = __float_as_uint(ha_sm[(r + 8) * HS + col]);
                        A[kk][h][2] = __float_as_uint(ha_sm[r * HS + col + 4]);
                        A[kk][h][3] = __float_as_uint(ha_sm[(r + 8) * HS + col + 4]);
                    }
                }
            }
            #pragma unroll
            for (int m = 0; m < 4; ++m) {
                int jt = jt0 + 4 * m;
                if (jt < 13) {
                    int jr = jt * 8 + g;
                    #pragma unroll
                    for (int kk = 0; kk < 2; ++kk) {
                        int colb = (2 * kc + kk) * 8 + t4;
                        unsigned B0 = __float_as_uint(h_sm[jr * HS + colb]);
                        unsigned B1 = __float_as_uint(h_sm[jr * HS + colb + 4]);
                        mma_tf32(c[m][0], A[kk][0], B0, B1);
                        if (nh == 2) mma_tf32(c[m][1], A[kk][1], B0, B1);
                    }
                }
            }
        }

        // epilogue: leaky-relu + select by adj == k+1
        #pragma unroll
        for (int m = 0; m < 4; ++m) {
            int jt = jt0 + 4 * m;
            if (jt < 13) {
                int col0 = jt * 8 + t4 * 2;
                #pragma unroll
                for (int h = 0; h < 2; ++h) {
                    if (h < nh) {
                        int r0 = row0 + h * 16 + g;
                        #pragma unroll
                        for (int rr = 0; rr < 4; ++rr) {
                            int row = r0 + ((rr >= 2) ? 8 : 0);
                            int col = col0 + (rr & 1);
                            if (row < L_) {
                                float v = c[m][h][rr];
                                v = (v > 0.f) ? v : 0.2f * v;
                                if (adj_sm[row * ADJS + col] == (char)(k + 1))
                                    al_sm[row * AS + col] = v;
                            }
                        }
                    }
                }
            }
        }
        __syncthreads();
    }

    // ---------------- phase 2: softmax over j ----------------
    for (int i = w; i < L_; i += 16) {
        float x[4];
        #pragma unroll
        for (int q = 0; q < 4; ++q) {
            int j = lane + 32 * q;
            x[q] = (j < L_) ? al_sm[i * AS + j] : NEG_INF_;
        }
        float mx = fmaxf(fmaxf(x[0], x[1]), fmaxf(x[2], x[3]));
        #pragma unroll
        for (int o = 16; o > 0; o >>= 1) mx = fmaxf(mx, __shfl_xor_sync(0xffffffffu, mx, o));
        float ev[4], s = 0.f;
        #pragma unroll
        for (int q = 0; q < 4; ++q) {
            int j = lane + 32 * q;
            ev[q] = (j < L_) ? __expf(x[q] - mx) : 0.f;
            s += ev[q];
        }
        #pragma unroll
        for (int o = 16; o > 0; o >>= 1) s += __shfl_xor_sync(0xffffffffu, s, o);
        float inv = 1.f / s;
        #pragma unroll
        for (int q = 0; q < 4; ++q) {
            int j = lane + 32 * q;
            if (j < L_)      al_sm[i * AS + j] = rna_tf32(ev[q] * inv);
            else if (j < AS) al_sm[i * AS + j] = 0.f;
        }
    }
    for (int e = tid; e < (MROWS - L_) * AS; e += 512) al_sm[L_ * AS + e] = 0.f;
    __syncthreads();

    // ---------------- phase 3: GEMM2  out = alpha @ h ----------------
    {
        const int nt = w;   // 16 n-tiles of 8 cols over D=128
        unsigned B0r[13], B1r[13];
        #pragma unroll
        for (int kt = 0; kt < 13; ++kt) {
            int jr = kt * 8 + t4;
            B0r[kt] = __float_as_uint(h_sm[jr * HS + nt * 8 + g]);
            B1r[kt] = __float_as_uint(h_sm[(jr + 4) * HS + nt * 8 + g]);
        }
        float* outb = out + (size_t)b * (L_ * D_);
        for (int i32 = 0; i32 < 4; ++i32) {
            int nh2 = (i32 == 3) ? 1 : 2;
            int r0b = i32 * 32;
            float c2[2][4];
            #pragma unroll
            for (int h = 0; h < 2; ++h)
                #pragma unroll
                for (int r = 0; r < 4; ++r) c2[h][r] = 0.f;

            #pragma unroll
            for (int kt = 0; kt < 13; ++kt) {
                #pragma unroll
                for (int h = 0; h < 2; ++h) {
                    if (h < nh2) {
                        int r = r0b + h * 16 + g;
                        int col = kt * 8 + t4;
                        unsigned A2[4];
                        A2[0] = __float_as_uint(al_sm[r * AS + col]);
                        A2[1] = __float_as_uint(al_sm[(r + 8) * AS + col]);
                        A2[2] = __float_as_uint(al_sm[r * AS + col + 4]);
                        A2[3] = __float_as_uint(al_sm[(r + 8) * AS + col + 4]);
                        mma_tf32(c2[h], A2, B0r[kt], B1r[kt]);
                    }
                }
            }
            #pragma unroll
            for (int h = 0; h < 2; ++h) {
                if (h < nh2) {
                    #pragma unroll
                    for (int p = 0; p < 2; ++p) {
                        int row = r0b + h * 16 + g + p * 8;
                        if (row < L_) {
                            int col = nt * 8 + t4 * 2;
                            float2 v2 = make_float2(c2[h][p * 2], c2[h][p * 2 + 1]);
                            *(float2*)(outb + row * D_ + col) = v2;
                        }
                    }
                }
            }
        }
    }
}

extern "C" void kernel_launch(void* const* d_in, const int* in_sizes, int n_in,
                              void* d_out, int out_size) {
    // metadata order: inputs, adj, mask_item, item, emb_table, a0, a1, a2, a3
    const int*   inputs = (const int*)d_in[0];
    const int*   adj    = (const int*)d_in[1];
    const float* emb    = (const float*)d_in[4];
    const float* a0     = (const float*)d_in[5];
    const float* a1     = (const float*)d_in[6];
    const float* a2     = (const float*)d_in[7];
    const float* a3     = (const float*)d_in[8];
    float* out = (float*)d_out;

    size_t smem = (size_t)(104 * HS + MROWS * HS + MROWS * AS + 4 * 128) * sizeof(float)
                + (size_t)L_ * ADJS;   // 174,880 B

    cudaFuncSetAttribute(combine_graph_kernel,
                         cudaFuncAttributeMaxDynamicSharedMemorySize, (int)smem);

    combine_graph_kernel<<<B_, 512, smem>>>(inputs, adj, emb, a0, a1, a2, a3, out);
}

// round 2
// speedup vs baseline: 1.5687x; 1.5687x over previous
#include <cuda_runtime.h>
#include <cstdint>
#include <cstddef>

// CombineGraph: h = emb[inputs]; e_k = leakyrelu(einsum(bid,bjd,d->bij; h,h,a_k));
// alpha = softmax(select_by_adj(e_k, -9e15)); out = alpha @ h.
// B=512, L=100, D=128. One CTA per batch (occ 2), tf32 mma.sync, k-inner fused GEMM1.

#define B_    512
#define L_    100
#define D_    128
#define HS    132      // h row stride (floats): (g*HS+t4)%32 = g*4+t4 -> conflict-free
#define AS    108      // alpha row stride
#define ADJS  112      // adj row stride (bytes)
#define NEG_INF_ -9e15f

__device__ __forceinline__ float rna_tf32(float x) {
    unsigned u;
    asm("cvt.rna.tf32.f32 %0, %1;" : "=r"(u) : "f"(x));
    return __uint_as_float(u);
}

__device__ __forceinline__ void mma_tf32(float* c, const unsigned* a, unsigned b0, unsigned b1) {
    asm volatile(
        "mma.sync.aligned.m16n8k8.row.col.f32.tf32.tf32.f32 "
        "{%0,%1,%2,%3},{%4,%5,%6,%7},{%8,%9},{%0,%1,%2,%3};\n"
        : "+f"(c[0]), "+f"(c[1]), "+f"(c[2]), "+f"(c[3])
        : "r"(a[0]), "r"(a[1]), "r"(a[2]), "r"(a[3]), "r"(b0), "r"(b1));
}

__global__ __launch_bounds__(512, 2)
void combine_graph_kernel(const int* __restrict__ inputs,
                          const int* __restrict__ adj,
                          const float* __restrict__ emb,
                          const float* __restrict__ a0p,
                          const float* __restrict__ a1p,
                          const float* __restrict__ a2p,
                          const float* __restrict__ a3p,
                          float* __restrict__ out)
{
    extern __shared__ char smem_raw[];
    float* h_sm   = (float*)smem_raw;               // 104 x 132
    float* al_sm  = h_sm  + 104 * HS;               // 104 x 108
    float* at_sm  = al_sm + 104 * AS;               // 128 x 4  (a transposed: at[d][k])
    char*  adj_sm = (char*)(at_sm + 128 * 4);       // 100 x 112 (int8)

    const int b    = blockIdx.x;
    const int tid  = threadIdx.x;
    const int w    = tid >> 5;
    const int lane = tid & 31;
    const int g    = lane >> 2;    // groupID (0..7)
    const int t4   = lane & 3;     // threadID_in_group (0..3)

    const int* inp  = inputs + b * L_;
    const int* adjb = adj + (size_t)b * (L_ * L_);

    // ---------------- phase 0: loads ----------------
    {   // a vectors transposed: at[d*4 + k] = a_k[d]
        int k = tid & 3, d = tid >> 2;
        const float* ap = (k == 0) ? a0p : (k == 1) ? a1p : (k == 2) ? a2p : a3p;
        at_sm[d * 4 + k] = ap[d];
    }
    // embedding gather -> h_sm (tf32-rounded); rows 100..103 zero
    for (int e = tid; e < 104 * 32; e += 512) {
        int r = e >> 5, q = e & 31;
        float4 v = make_float4(0.f, 0.f, 0.f, 0.f);
        if (r < L_) {
            int id = inp[r];
            v = ((const float4*)(emb + (size_t)id * D_))[q];
            v.x = rna_tf32(v.x); v.y = rna_tf32(v.y);
            v.z = rna_tf32(v.z); v.w = rna_tf32(v.w);
        }
        *(float4*)(h_sm + r * HS + q * 4) = v;
    }
    // adj -> int8 shared (cols 100..111 zero-padded)
    for (int e = tid; e < 2500; e += 512) {
        int i = e / 25, c = e % 25;
        int4 v = ((const int4*)(adjb + i * 100))[c];
        unsigned p = (unsigned)(v.x & 0xff) | ((unsigned)(v.y & 0xff) << 8)
                   | ((unsigned)(v.z & 0xff) << 16) | ((unsigned)(v.w & 0xff) << 24);
        *(unsigned*)(adj_sm + i * ADJS + c * 4) = p;
    }
    if (tid < 300) {
        int i = tid / 3, c = tid % 3;
        *(unsigned*)(adj_sm + i * ADJS + 100 + c * 4) = 0u;
    }
    __syncthreads();

    // ---------- phase 1: fused GEMM1 (all 4 edge types in one pass) ----------
    // grid of jobs: 7 m16-tiles x 7 n16-pairs = 49; job 48 is half-sized.
    for (int job = w; job < 49; job += 16) {
        int mt = job / 7, np = job % 7;
        int r0  = mt * 16;
        int nc0 = np * 16;
        const bool mguard = (mt == 6);         // rows 104..111 don't exist
        const int  nnmax  = (np == 6) ? 1 : 2; // cols 104..111 not needed

        float c[2][4][4];
        #pragma unroll
        for (int nn = 0; nn < 2; ++nn)
            #pragma unroll
            for (int k = 0; k < 4; ++k)
                #pragma unroll
                for (int r = 0; r < 4; ++r) c[nn][k][r] = 0.f;

        #pragma unroll 4
        for (int ks = 0; ks < 16; ++ks) {
            int col = ks * 8 + t4;
            unsigned A[4];
            A[0] = __float_as_uint(h_sm[(r0 + g) * HS + col]);
            A[1] = mguard ? 0u : __float_as_uint(h_sm[(r0 + 8 + g) * HS + col]);
            A[2] = __float_as_uint(h_sm[(r0 + g) * HS + col + 4]);
            A[3] = mguard ? 0u : __float_as_uint(h_sm[(r0 + 8 + g) * HS + col + 4]);
            float4 aa = *(const float4*)(at_sm + col * 4);
            float4 ab = *(const float4*)(at_sm + (col + 4) * 4);
            #pragma unroll
            for (int nn = 0; nn < 2; ++nn) {
                if (nn < nnmax) {
                    int jr = nc0 + nn * 8 + g;
                    float B0 = h_sm[jr * HS + col];
                    float B1 = h_sm[jr * HS + col + 4];
                    mma_tf32(c[nn][0], A, __float_as_uint(B0 * aa.x), __float_as_uint(B1 * ab.x));
                    mma_tf32(c[nn][1], A, __float_as_uint(B0 * aa.y), __float_as_uint(B1 * ab.y));
                    mma_tf32(c[nn][2], A, __float_as_uint(B0 * aa.z), __float_as_uint(B1 * ab.z));
                    mma_tf32(c[nn][3], A, __float_as_uint(B0 * aa.w), __float_as_uint(B1 * ab.w));
                }
            }
        }
        // epilogue: select by adj, leaky-relu, single write
        #pragma unroll
        for (int nn = 0; nn < 2; ++nn) {
            if (nn < nnmax) {
                #pragma unroll
                for (int p = 0; p < 4; ++p) {
                    int row = r0 + g + ((p >= 2) ? 8 : 0);
                    int col = nc0 + nn * 8 + t4 * 2 + (p & 1);
                    if (row < L_) {
                        int t = adj_sm[row * ADJS + col];
                        float v = (t == 1) ? c[nn][0][p] :
                                  (t == 2) ? c[nn][1][p] :
                                  (t == 3) ? c[nn][2][p] : c[nn][3][p];
                        v = (v > 0.f) ? v : 0.2f * v;
                        al_sm[row * AS + col] = t ? v : NEG_INF_;
                    }
                }
            }
        }
    }
    __syncthreads();

    // ---------------- phase 2: softmax over j + padding ----------------
    for (int i = w; i < L_; i += 16) {
        float x[4];
        #pragma unroll
        for (int q = 0; q < 4; ++q) {
            int j = lane + 32 * q;
            x[q] = (j < 104) ? al_sm[i * AS + j] : NEG_INF_;
        }
        float mx = fmaxf(fmaxf(x[0], x[1]), fmaxf(x[2], x[3]));
        #pragma unroll
        for (int o = 16; o > 0; o >>= 1) mx = fmaxf(mx, __shfl_xor_sync(0xffffffffu, mx, o));
        float ev[4], s = 0.f;
        #pragma unroll
        for (int q = 0; q < 4; ++q) {
            int j = lane + 32 * q;
            ev[q] = (j < L_) ? __expf(x[q] - mx) : 0.f;
            s += ev[q];
        }
        #pragma unroll
        for (int o = 16; o > 0; o >>= 1) s += __shfl_xor_sync(0xffffffffu, s, o);
        float inv = 1.f / s;
        #pragma unroll
        for (int q = 0; q < 4; ++q) {
            int j = lane + 32 * q;
            if (j < L_)      al_sm[i * AS + j] = rna_tf32(ev[q] * inv);
            else if (j < 104) al_sm[i * AS + j] = 0.f;
        }
    }
    // zero alpha rows 100..103 (GEMM2 reads them as K padding)
    for (int e = tid; e < 4 * AS; e += 512) al_sm[L_ * AS + e] = 0.f;
    __syncthreads();

    // ---------------- phase 3: GEMM2  out = alpha @ h ----------------
    // warp w -> n-tiles {2*(w&7), 2*(w&7)+1}, i32-tiles {0,1} or {2,3}
    {
        const int nA = (w & 7) * 2;
        const int ih = (w >> 3) * 2;
        float* outb = out + (size_t)b * (L_ * D_);
        #pragma unroll
        for (int ii = 0; ii < 2; ++ii) {
            int i32 = ih + ii;
            int nh2 = (i32 == 3) ? 1 : 2;
            int r0b = i32 * 32;
            float c2[2][2][4];   // [nn][h][reg]
            #pragma unroll
            for (int nn = 0; nn < 2; ++nn)
                #pragma unroll
                for (int h = 0; h < 2; ++h)
                    #pragma unroll
                    for (int r = 0; r < 4; ++r) c2[nn][h][r] = 0.f;

            #pragma unroll 4
            for (int kt = 0; kt < 13; ++kt) {
                int col = kt * 8 + t4;
                unsigned A2[2][4];
                #pragma unroll
                for (int h = 0; h < 2; ++h) {
                    if (h < nh2) {
                        int r = r0b + h * 16 + g;
                        A2[h][0] = __float_as_uint(al_sm[r * AS + col]);
                        A2[h][1] = (i32 == 3) ? 0u : __float_as_uint(al_sm[(r + 8) * AS + col]);
                        A2[h][2] = __float_as_uint(al_sm[r * AS + col + 4]);
                        A2[h][3] = (i32 == 3) ? 0u : __float_as_uint(al_sm[(r + 8) * AS + col + 4]);
                    }
                }
                #pragma unroll
                for (int nn = 0; nn < 2; ++nn) {
                    int nt = nA + nn;
                    unsigned B0 = __float_as_uint(h_sm[(kt * 8 + t4) * HS + nt * 8 + g]);
                    unsigned B1 = __float_as_uint(h_sm[(kt * 8 + t4 + 4) * HS + nt * 8 + g]);
                    mma_tf32(c2[nn][0], A2[0], B0, B1);
                    if (nh2 == 2) mma_tf32(c2[nn][1], A2[1], B0, B1);
                }
            }
            #pragma unroll
            for (int nn = 0; nn < 2; ++nn) {
                #pragma unroll
                for (int h = 0; h < 2; ++h) {
                    if (h < nh2) {
                        #pragma unroll
                        for (int p = 0; p < 2; ++p) {
                            int row = r0b + h * 16 + g + p * 8;
                            if (row < L_) {
                                int colo = (nA + nn) * 8 + t4 * 2;
                                float2 v2 = make_float2(c2[nn][h][p * 2], c2[nn][h][p * 2 + 1]);
                                *(float2*)(outb + row * D_ + colo) = v2;
                            }
                        }
                    }
                }
            }
        }
    }
}

extern "C" void kernel_launch(void* const* d_in, const int* in_sizes, int n_in,
                              void* d_out, int out_size) {
    // metadata order: inputs, adj, mask_item, item, emb_table, a0, a1, a2, a3
    const int*   inputs = (const int*)d_in[0];
    const int*   adj    = (const int*)d_in[1];
    const float* emb    = (const float*)d_in[4];
    const float* a0     = (const float*)d_in[5];
    const float* a1     = (const float*)d_in[6];
    const float* a2     = (const float*)d_in[7];
    const float* a3     = (const float*)d_in[8];
    float* out = (float*)d_out;

    size_t smem = (size_t)(104 * HS + 104 * AS + 128 * 4) * sizeof(float)
                + (size_t)L_ * ADJS;   // 113,088 B -> 2 CTAs/SM

    cudaFuncSetAttribute(combine_graph_kernel,
                         cudaFuncAttributeMaxDynamicSharedMemorySize, (int)smem);

    combine_graph_kernel<<<B_, 512, smem>>>(inputs, adj, emb, a0, a1, a2, a3, out);
}

// round 4
// speedup vs baseline: 1.9765x; 1.2600x over previous
#include <cuda_runtime.h>
#include <cuda_bf16.h>
#include <cstdint>
#include <cstddef>

// CombineGraph: h = emb[inputs]; e_k = leakyrelu(einsum(bid,bjd,d->bij; h,h,a_k));
// alpha = softmax(select_by_adj(e_k, -9e15)); out = alpha @ h.
// B=512, L=100, D=128. One CTA/batch, 2 CTA/SM.
// GEMM1: bf16 mma.sync m16n8k16, B scaled by packed a_k in regs, results staged
// in registers then written to al (overlaying dead h_bf/adj). GEMM2: tf32 mma.sync.

#define B_    512
#define L_    100
#define D_    128
#define HS    132      // h f32 row stride (floats)
#define HB    68       // h bf16 row stride (bf16x2 words): (68g+t4)%32 = 4g+t4 -> conflict-free
#define AS    108      // alpha row stride (floats)
#define ADJS  112      // adj row stride (bytes)
#define NEG_INF_ -9e15f

// ---- smem byte offsets ----
#define OFF_H    0                       // h f32: 104*132*4 = 54912
#define OFF_HBF  54912                   // h bf16: 104*68*4 = 28288
#define OFF_ATP  83200                   // a packed bf16x2: 64 words x 4 types x 4B = 1024
#define OFF_ADJ  84224                   // adj int8: 100*112 = 11200 (ends 95424)
#define OFF_AL   54912                   // alpha f32 overlays h_bf/atp/adj: 104*108*4 = 44928
#define SMEM_TOTAL 99840

__device__ __forceinline__ float rna_tf32(float x) {
    unsigned u; asm("cvt.rna.tf32.f32 %0, %1;" : "=r"(u) : "f"(x));
    return __uint_as_float(u);
}
__device__ __forceinline__ unsigned pack_bf16x2(float lo, float hi) {
    unsigned r; asm("cvt.rn.satfinite.bf16x2.f32 %0, %1, %2;" : "=r"(r) : "f"(hi), "f"(lo));
    return r;
}
__device__ __forceinline__ unsigned mulbf2(unsigned a, unsigned b) {
    unsigned r; asm("mul.bf16x2 %0, %1, %2;" : "=r"(r) : "r"(a), "r"(b));
    return r;
}
__device__ __forceinline__ void mma_bf16(float* c, const unsigned* a, unsigned b0, unsigned b1) {
    asm volatile(
        "mma.sync.aligned.m16n8k16.row.col.f32.bf16.bf16.f32 "
        "{%0,%1,%2,%3},{%4,%5,%6,%7},{%8,%9},{%0,%1,%2,%3};\n"
        : "+f"(c[0]), "+f"(c[1]), "+f"(c[2]), "+f"(c[3])
        : "r"(a[0]), "r"(a[1]), "r"(a[2]), "r"(a[3]), "r"(b0), "r"(b1));
}
__device__ __forceinline__ void mma_tf32(float* c, const unsigned* a, unsigned b0, unsigned b1) {
    asm volatile(
        "mma.sync.aligned.m16n8k8.row.col.f32.tf32.tf32.f32 "
        "{%0,%1,%2,%3},{%4,%5,%6,%7},{%8,%9},{%0,%1,%2,%3};\n"
        : "+f"(c[0]), "+f"(c[1]), "+f"(c[2]), "+f"(c[3])
        : "r"(a[0]), "r"(a[1]), "r"(a[2]), "r"(a[3]), "r"(b0), "r"(b1));
}

__global__ __launch_bounds__(512, 2)
void combine_graph_kernel(const int* __restrict__ inputs,
                          const int* __restrict__ adj,
                          const float* __restrict__ emb,
                          const float* __restrict__ a0p,
                          const float* __restrict__ a1p,
                          const float* __restrict__ a2p,
                          const float* __restrict__ a3p,
                          float* __restrict__ out)
{
    extern __shared__ char smem[];
    float*    h_sm   = (float*)(smem + OFF_H);
    unsigned* hb_sm  = (unsigned*)(smem + OFF_HBF);
    unsigned* atp_sm = (unsigned*)(smem + OFF_ATP);
    char*     adj_sm = smem + OFF_ADJ;
    float*    al_sm  = (float*)(smem + OFF_AL);

    const int b    = blockIdx.x;
    const int tid  = threadIdx.x;
    const int w    = tid >> 5;
    const int lane = tid & 31;
    const int g    = lane >> 2;
    const int t4   = lane & 3;

    const int* inp  = inputs + b * L_;
    const int* adjb = adj + (size_t)b * (L_ * L_);

    // ---------------- phase 0: loads ----------------
    if (tid < 256) {   // a_k packed bf16x2: atp[word*4 + k]
        int wd = tid & 63, k = tid >> 6;
        const float* ap = (k == 0) ? a0p : (k == 1) ? a1p : (k == 2) ? a2p : a3p;
        atp_sm[wd * 4 + k] = pack_bf16x2(ap[2 * wd], ap[2 * wd + 1]);
    }
    // embedding gather -> h f32 (tf32-rounded) + h bf16; rows 100..103 zero
    for (int e = tid; e < 104 * 32; e += 512) {
        int r = e >> 5, q = e & 31;
        float4 v = make_float4(0.f, 0.f, 0.f, 0.f);
        if (r < L_) {
            int id = inp[r];
            v = ((const float4*)(emb + (size_t)id * D_))[q];
            v.x = rna_tf32(v.x); v.y = rna_tf32(v.y);
            v.z = rna_tf32(v.z); v.w = rna_tf32(v.w);
        }
        *(float4*)(h_sm + r * HS + q * 4) = v;
        hb_sm[r * HB + 2 * q]     = pack_bf16x2(v.x, v.y);
        hb_sm[r * HB + 2 * q + 1] = pack_bf16x2(v.z, v.w);
    }
    // adj -> int8
    for (int e = tid; e < 2500; e += 512) {
        int i = e / 25, c = e % 25;
        int4 v = ((const int4*)(adjb + i * 100))[c];
        unsigned p = (unsigned)(v.x & 0xff) | ((unsigned)(v.y & 0xff) << 8)
                   | ((unsigned)(v.z & 0xff) << 16) | ((unsigned)(v.w & 0xff) << 24);
        *(unsigned*)(adj_sm + i * ADJS + c * 4) = p;
    }
    __syncthreads();

    // ---------- phase 1: GEMM1 (bf16 m16n8k16; all 4 edge types fused) ----------
    // jobs: 7 m16-tiles x 7 n16-pairs = 49; results staged in regs (bf16x2).
    unsigned stg[4][2][2];
    const uint4* at4 = (const uint4*)atp_sm;
    #pragma unroll
    for (int jj = 0; jj < 4; ++jj) {
        int job = w + jj * 16;
        if (job < 49) {
            int mt = job / 7, np = job % 7;
            int r0  = mt * 16;
            int jc0 = np * 16;
            const bool mguard = (mt == 6);
            const int  nnmax  = (np == 6) ? 1 : 2;

            float c[2][4][4];
            #pragma unroll
            for (int nn = 0; nn < 2; ++nn)
                #pragma unroll
                for (int k = 0; k < 4; ++k)
                    #pragma unroll
                    for (int r = 0; r < 4; ++r) c[nn][k][r] = 0.f;

            #pragma unroll 2
            for (int ks = 0; ks < 8; ++ks) {
                int wd = ks * 8 + t4;
                unsigned A[4];
                A[0] = hb_sm[(r0 + g) * HB + wd];
                A[1] = mguard ? 0u : hb_sm[(r0 + 8 + g) * HB + wd];
                A[2] = hb_sm[(r0 + g) * HB + wd + 4];
                A[3] = mguard ? 0u : hb_sm[(r0 + 8 + g) * HB + wd + 4];
                uint4 ap0 = at4[wd];
                uint4 ap1 = at4[wd + 4];
                #pragma unroll
                for (int nn = 0; nn < 2; ++nn) {
                    if (nn < nnmax) {
                        int jr = jc0 + nn * 8 + g;
                        unsigned B0 = hb_sm[jr * HB + wd];
                        unsigned B1 = hb_sm[jr * HB + wd + 4];
                        mma_bf16(c[nn][0], A, mulbf2(B0, ap0.x), mulbf2(B1, ap1.x));
                        mma_bf16(c[nn][1], A, mulbf2(B0, ap0.y), mulbf2(B1, ap1.y));
                        mma_bf16(c[nn][2], A, mulbf2(B0, ap0.z), mulbf2(B1, ap1.z));
                        mma_bf16(c[nn][3], A, mulbf2(B0, ap0.w), mulbf2(B1, ap1.w));
                    }
                }
            }
            // select by adj + leaky-relu -> staged bf16x2
            #pragma unroll
            for (int nn = 0; nn < 2; ++nn) {
                #pragma unroll
                for (int hf = 0; hf < 2; ++hf) {
                    int row = r0 + g + hf * 8;
                    float v[2];
                    #pragma unroll
                    for (int e = 0; e < 2; ++e) {
                        int col = jc0 + nn * 8 + 2 * t4 + e;
                        int p = hf * 2 + e;
                        float val = NEG_INF_;
                        if (nn < nnmax && row < L_ && col < L_) {
                            int t = adj_sm[row * ADJS + col];
                            float x = (t == 1) ? c[nn][0][p] :
                                      (t == 2) ? c[nn][1][p] :
                                      (t == 3) ? c[nn][2][p] : c[nn][3][p];
                            x = (x > 0.f) ? x : 0.2f * x;
                            val = t ? x : NEG_INF_;
                        }
                        v[e] = val;
                    }
                    stg[jj][nn][hf] = pack_bf16x2(v[0], v[1]);
                }
            }
        }
    }
    __syncthreads();   // h_bf / adj dead; al overlay becomes valid

    // write staged logits to al
    #pragma unroll
    for (int jj = 0; jj < 4; ++jj) {
        int job = w + jj * 16;
        if (job < 49) {
            int mt = job / 7, np = job % 7;
            int r0 = mt * 16, jc0 = np * 16;
            #pragma unroll
            for (int nn = 0; nn < 2; ++nn) {
                int col0 = jc0 + nn * 8 + 2 * t4;
                if (col0 < 104) {
                    #pragma unroll
                    for (int hf = 0; hf < 2; ++hf) {
                        int row = r0 + g + hf * 8;
                        if (row < 104) {
                            unsigned pk = stg[jj][nn][hf];
                            float2 vv = make_float2(__uint_as_float(pk << 16),
                                                    __uint_as_float(pk & 0xffff0000u));
                            *(float2*)(al_sm + row * AS + col0) = vv;
                        }
                    }
                }
            }
        }
    }
    __syncthreads();

    // ---------------- phase 2: softmax over j ----------------
    for (int i = w; i < L_; i += 16) {
        float x[4];
        #pragma unroll
        for (int q = 0; q < 4; ++q) {
            int j = lane + 32 * q;
            x[q] = (j < 104) ? al_sm[i * AS + j] : NEG_INF_;
        }
        float mx = fmaxf(fmaxf(x[0], x[1]), fmaxf(x[2], x[3]));
        #pragma unroll
        for (int o = 16; o > 0; o >>= 1) mx = fmaxf(mx, __shfl_xor_sync(0xffffffffu, mx, o));
        float ev[4], s = 0.f;
        #pragma unroll
        for (int q = 0; q < 4; ++q) {
            int j = lane + 32 * q;
            ev[q] = (j < L_) ? __expf(x[q] - mx) : 0.f;
            s += ev[q];
        }
        #pragma unroll
        for (int o = 16; o > 0; o >>= 1) s += __shfl_xor_sync(0xffffffffu, s, o);
        float inv = 1.f / s;
        #pragma unroll
        for (int q = 0; q < 4; ++q) {
            int j = lane + 32 * q;
            if (j < L_)       al_sm[i * AS + j] = rna_tf32(ev[q] * inv);
            else if (j < 104) al_sm[i * AS + j] = 0.f;
        }
    }
    // zero alpha rows 100..103 (GEMM2 K padding)
    for (int e = tid; e < 4 * AS; e += 512) al_sm[L_ * AS + e] = 0.f;
    __syncthreads();

    // ---------------- phase 3: GEMM2  out = alpha @ h  (tf32) ----------------
    {
        const int nA = (w & 7) * 2;
        const int ih = (w >> 3) * 2;
        float* outb = out + (size_t)b * (L_ * D_);
        #pragma unroll
        for (int ii = 0; ii < 2; ++ii) {
            int i32 = ih + ii;
            int nh2 = (i32 == 3) ? 1 : 2;
            int r0b = i32 * 32;
            float c2[2][2][4];
            #pragma unroll
            for (int nn = 0; nn < 2; ++nn)
                #pragma unroll
                for (int h = 0; h < 2; ++h)
                    #pragma unroll
                    for (int r = 0; r < 4; ++r) c2[nn][h][r] = 0.f;

            #pragma unroll 4
            for (int kt = 0; kt < 13; ++kt) {
                int col = kt * 8 + t4;
                unsigned A2[2][4];
                #pragma unroll
                for (int h = 0; h < 2; ++h) {
                    if (h < nh2) {
                        int r = r0b + h * 16 + g;
                        A2[h][0] = __float_as_uint(al_sm[r * AS + col]);
                        A2[h][1] = (i32 == 3) ? 0u : __float_as_uint(al_sm[(r + 8) * AS + col]);
                        A2[h][2] = __float_as_uint(al_sm[r * AS + col + 4]);
                        A2[h][3] = (i32 == 3) ? 0u : __float_as_uint(al_sm[(r + 8) * AS + col + 4]);
                    }
                }
                #pragma unroll
                for (int nn = 0; nn < 2; ++nn) {
                    int nt = nA + nn;
                    unsigned B0 = __float_as_uint(h_sm[(kt * 8 + t4) * HS + nt * 8 + g]);
                    unsigned B1 = __float_as_uint(h_sm[(kt * 8 + t4 + 4) * HS + nt * 8 + g]);
                    mma_tf32(c2[nn][0], A2[0], B0, B1);
                    if (nh2 == 2) mma_tf32(c2[nn][1], A2[1], B0, B1);
                }
            }
            #pragma unroll
            for (int nn = 0; nn < 2; ++nn) {
                #pragma unroll
                for (int h = 0; h < 2; ++h) {
                    if (h < nh2) {
                        #pragma unroll
                        for (int p = 0; p < 2; ++p) {
                            int row = r0b + h * 16 + g + p * 8;
                            if (row < L_) {
                                int colo = (nA + nn) * 8 + t4 * 2;
                                float2 v2 = make_float2(c2[nn][h][p * 2], c2[nn][h][p * 2 + 1]);
                                *(float2*)(outb + row * D_ + colo) = v2;
                            }
                        }
                    }
                }
            }
        }
    }
}

extern "C" void kernel_launch(void* const* d_in, const int* in_sizes, int n_in,
                              void* d_out, int out_size) {
    // metadata order: inputs, adj, mask_item, item, emb_table, a0, a1, a2, a3
    const int*   inputs = (const int*)d_in[0];
    const int*   adj    = (const int*)d_in[1];
    const float* emb    = (const float*)d_in[4];
    const float* a0     = (const float*)d_in[5];
    const float* a1     = (const float*)d_in[6];
    const float* a2     = (const float*)d_in[7];
    const float* a3     = (const float*)d_in[8];
    float* out = (float*)d_out;

    cudaFuncSetAttribute(combine_graph_kernel,
                         cudaFuncAttributeMaxDynamicSharedMemorySize, SMEM_TOTAL);

    combine_graph_kernel<<<B_, 512, SMEM_TOTAL>>>(inputs, adj, emb, a0, a1, a2, a3, out);
}